// round 8
// baseline (speedup 1.0000x reference)
#include <cuda_runtime.h>

#define N_NODES 50000
#define F_IN    96
#define HID     128
#define OUTF    64
#define N_EDGES 800000
#define NT      64   // nodes per block in fused kernel

// ---------------- device scratch (allowed: __device__ globals) ----------------
__device__ float g_agg[N_NODES * F_IN];      // layer-1 aggregation  (19.2 MB)
__device__ float g_hr [N_NODES * OUTF];      // h @ W2_rel^T         (12.8 MB)
__device__ float g_W1relT [F_IN * HID];      // k-major weights
__device__ float g_W1rootT[F_IN * HID];
__device__ float g_W2relT [HID * OUTF];
__device__ float g_W2rootT[HID * OUTF];
__device__ int   g_mode64;                   // 1 = edge_index is int64, 0 = int32

// ---------------- dtype probe: deterministic function of the input ----------------
__global__ void probe_kernel(const long long* __restrict__ p) {
    if (threadIdx.x == 0 && blockIdx.x == 0) {
        int ok = 1;
        for (int i = 0; i < 64; i++) {
            long long v = p[i];
            if (v < 0 || v >= N_NODES) ok = 0;  // int32 data reinterpreted -> huge values
        }
        g_mode64 = ok;
    }
}

// ---------------- zero the aggregation buffer ----------------
__global__ void zero_agg_kernel() {
    int i = blockIdx.x * blockDim.x + threadIdx.x;
    if (i < N_NODES * (F_IN / 4))
        ((float4*)g_agg)[i] = make_float4(0.f, 0.f, 0.f, 0.f);
}

// ---------------- transpose weights to k-major (tiny, once per launch) ----------------
__global__ void transpose_w_kernel(const float* __restrict__ W1rel,
                                   const float* __restrict__ W1root,
                                   const float* __restrict__ W2rel,
                                   const float* __restrict__ W2root) {
    int i = blockIdx.x * blockDim.x + threadIdx.x;
    if (i < HID * F_IN) {   // W1: [128 x 96] -> [96][128]
        int o = i / F_IN, k = i % F_IN;
        g_W1relT [k * HID + o] = W1rel[i];
        g_W1rootT[k * HID + o] = W1root[i];
    }
    if (i < OUTF * HID) {   // W2: [64 x 128] -> [128][64]
        int o = i / HID, k = i % HID;
        g_W2relT [k * OUTF + o] = W2rel[i];
        g_W2rootT[k * OUTF + o] = W2root[i];
    }
}

// ---------------- layer-1 scatter: agg_x[dst] += x[src]  (96 floats = 24 float4) ----------------
__global__ void scatter_x_kernel(const float* __restrict__ x, const void* __restrict__ ei) {
    const int CH = F_IN / 4;  // 24
    int i = blockIdx.x * blockDim.x + threadIdx.x;
    if (i >= N_EDGES * CH) return;
    int e = i / CH, c = i - e * CH;
    int src, dst;
    if (g_mode64) {
        const long long* p = (const long long*)ei;
        src = (int)__ldg(p + e);
        dst = (int)__ldg(p + N_EDGES + e);
    } else {
        const int* p = (const int*)ei;
        src = __ldg(p + e);
        dst = __ldg(p + N_EDGES + e);
    }
    if (src == dst) return;  // remove_self_loops
    float4 v = __ldg((const float4*)x + (size_t)src * CH + c);
    atomicAdd((float4*)g_agg + (size_t)dst * CH + c, v);  // sm_90+ vector atomic
}

// ---------------- layer-2 scatter: out[dst] += hr[src]  (64 floats = 16 float4) ----------------
__global__ void scatter_hr_kernel(const void* __restrict__ ei, float* __restrict__ out) {
    const int CH = OUTF / 4;  // 16
    int i = blockIdx.x * blockDim.x + threadIdx.x;
    if (i >= N_EDGES * CH) return;
    int e = i / CH, c = i - e * CH;
    int src, dst;
    if (g_mode64) {
        const long long* p = (const long long*)ei;
        src = (int)__ldg(p + e);
        dst = (int)__ldg(p + N_EDGES + e);
    } else {
        const int* p = (const int*)ei;
        src = __ldg(p + e);
        dst = __ldg(p + N_EDGES + e);
    }
    if (src == dst) return;
    float4 v = __ldg((const float4*)g_hr + (size_t)src * CH + c);
    atomicAdd((float4*)out + (size_t)dst * CH + c, v);
}

// ---------------- fused node kernel ----------------
// Per block: 64 nodes, 256 threads (8 warps; each warp owns 8 nodes).
// Stage 1: H[64][128] = relu(agg @ W1rel^T + x @ W1root^T + b1)  -> SMEM
// Stage 2: hr = H @ W2rel^T -> g_hr ;  out = H @ W2root^T + b2 -> d_out
// SMEM: region0 (16384 floats) = sA[64][96] | sX[64][96] | sW1[2][16][128]
//       (reused in stage 2 as W2relT[128][64] | W2rootT[128][64])
//       sH[64][128] (8192 floats).  Total 98304 B -> 2 blocks/SM.
__global__ __launch_bounds__(256, 2)
void fused_kernel(const float* __restrict__ x,
                  const float* __restrict__ b1,
                  const float* __restrict__ b2,
                  float* __restrict__ out) {
    extern __shared__ float smem[];
    float* sA = smem;                    // 6144
    float* sX = smem + NT * F_IN;        // 6144
    float* sW = smem + 2 * NT * F_IN;    // 4096 (two 16x128 chunks)
    float* sH = smem + 16384;            // 8192

    const int tid  = threadIdx.x;
    const int warp = tid >> 5;
    const int lane = tid & 31;
    const int nodeBase = blockIdx.x * NT;

    // ---- load agg & x tiles (node-major, coalesced float4) ----
    #pragma unroll
    for (int t = 0; t < 6; t++) {
        int i = tid + t * 256;            // 0 .. 1535
        int n = i / (F_IN / 4);
        int c = i - n * (F_IN / 4);
        int node = nodeBase + n;
        float4 va = make_float4(0.f, 0.f, 0.f, 0.f), vx = va;
        if (node < N_NODES) {
            va = __ldg((const float4*)g_agg + (size_t)node * (F_IN / 4) + c);
            vx = __ldg((const float4*)x    + (size_t)node * (F_IN / 4) + c);
        }
        ((float4*)sA)[i] = va;
        ((float4*)sX)[i] = vx;
    }

    // ---- stage 1: accumulators seeded with bias ----
    float acc[8][4];
    #pragma unroll
    for (int j = 0; j < 4; j++) {
        float bj = __ldg(b1 + lane + 32 * j);
        #pragma unroll
        for (int n = 0; n < 8; n++) acc[n][j] = bj;
    }

    const int KC = 16;
    for (int kc = 0; kc < F_IN / KC; kc++) {
        __syncthreads();  // protect sW reuse + (iter 0) tile-load completion
        #pragma unroll
        for (int t = 0; t < (KC * HID) / 256; t++) {   // 8 iters
            int i = tid + t * 256;
            sW[i]            = g_W1relT [kc * KC * HID + i];
            sW[KC * HID + i] = g_W1rootT[kc * KC * HID + i];
        }
        __syncthreads();
        #pragma unroll
        for (int kk = 0; kk < KC; kk++) {
            int k = kc * KC + kk;
            float wr[4], wo[4];
            #pragma unroll
            for (int j = 0; j < 4; j++) {
                wr[j] = sW[kk * HID + lane + 32 * j];             // lane-consecutive: conflict-free
                wo[j] = sW[KC * HID + kk * HID + lane + 32 * j];
            }
            #pragma unroll
            for (int n = 0; n < 8; n++) {
                float a  = sA[(warp * 8 + n) * F_IN + k];         // broadcast
                float xv = sX[(warp * 8 + n) * F_IN + k];         // broadcast
                #pragma unroll
                for (int j = 0; j < 4; j++)
                    acc[n][j] = fmaf(a, wr[j], fmaf(xv, wo[j], acc[n][j]));
            }
        }
    }

    // ---- relu -> sH (lane-consecutive stores: conflict-free) ----
    #pragma unroll
    for (int n = 0; n < 8; n++)
        #pragma unroll
        for (int j = 0; j < 4; j++)
            sH[(warp * 8 + n) * HID + lane + 32 * j] = fmaxf(acc[n][j], 0.f);
    __syncthreads();

    // ---- load W2 (k-major) over region0 ----
    #pragma unroll
    for (int t = 0; t < (HID * OUTF) / 256; t++) {  // 32 iters
        int i = tid + t * 256;
        smem[i]              = g_W2relT[i];
        smem[HID * OUTF + i] = g_W2rootT[i];
    }
    __syncthreads();

    // ---- stage 2 ----
    float accR[8][2], accO[8][2];
    #pragma unroll
    for (int j = 0; j < 2; j++) {
        float bj = __ldg(b2 + lane + 32 * j);
        #pragma unroll
        for (int n = 0; n < 8; n++) { accR[n][j] = 0.f; accO[n][j] = bj; }
    }
    #pragma unroll 4
    for (int k = 0; k < HID; k++) {
        float w2r[2], w2o[2];
        #pragma unroll
        for (int j = 0; j < 2; j++) {
            w2r[j] = smem[k * OUTF + lane + 32 * j];
            w2o[j] = smem[HID * OUTF + k * OUTF + lane + 32 * j];
        }
        #pragma unroll
        for (int n = 0; n < 8; n++) {
            float h = sH[(warp * 8 + n) * HID + k];   // broadcast
            #pragma unroll
            for (int j = 0; j < 2; j++) {
                accR[n][j] = fmaf(h, w2r[j], accR[n][j]);
                accO[n][j] = fmaf(h, w2o[j], accO[n][j]);
            }
        }
    }

    // ---- write hr and partial out (root path + bias) ----
    #pragma unroll
    for (int n = 0; n < 8; n++) {
        int node = nodeBase + warp * 8 + n;
        if (node < N_NODES) {
            #pragma unroll
            for (int j = 0; j < 2; j++) {
                g_hr[(size_t)node * OUTF + lane + 32 * j] = accR[n][j];
                out [(size_t)node * OUTF + lane + 32 * j] = accO[n][j];
            }
        }
    }
}

// ---------------- launch ----------------
extern "C" void kernel_launch(void* const* d_in, const int* in_sizes, int n_in,
                              void* d_out, int out_size) {
    const float* x      = (const float*)d_in[0];
    const void*  ei     = d_in[1];
    const float* W1rel  = (const float*)d_in[2];
    const float* b1     = (const float*)d_in[3];
    const float* W1root = (const float*)d_in[4];
    const float* W2rel  = (const float*)d_in[5];
    const float* b2     = (const float*)d_in[6];
    const float* W2root = (const float*)d_in[7];
    float* out = (float*)d_out;

    const int SMEM_BYTES = (16384 + NT * HID) * (int)sizeof(float);  // 98304
    cudaFuncSetAttribute(fused_kernel,
                         cudaFuncAttributeMaxDynamicSharedMemorySize, SMEM_BYTES);

    probe_kernel<<<1, 32>>>((const long long*)ei);
    zero_agg_kernel<<<(N_NODES * (F_IN / 4) + 255) / 256, 256>>>();
    transpose_w_kernel<<<(HID * F_IN + 255) / 256, 256>>>(W1rel, W1root, W2rel, W2root);
    scatter_x_kernel<<<(N_EDGES * (F_IN / 4) + 255) / 256, 256>>>(x, ei);
    fused_kernel<<<(N_NODES + NT - 1) / NT, 256, SMEM_BYTES>>>(x, b1, b2, out);
    scatter_hr_kernel<<<(N_EDGES * (OUTF / 4) + 255) / 256, 256>>>(ei, out);
}

// round 9
// speedup vs baseline: 1.0003x; 1.0003x over previous
#include <cuda_runtime.h>

#define N_NODES 50000
#define F_IN    96
#define HID     128
#define OUTF    64
#define N_EDGES 800000
#define NT      64   // nodes per block in fused kernel

// ---------------- device scratch (allowed: __device__ globals) ----------------
__device__ float g_agg[N_NODES * F_IN];      // layer-1 aggregation  (19.2 MB)
__device__ float g_hr [N_NODES * OUTF];      // h @ W2_rel^T         (12.8 MB)
__device__ float g_W1relT [F_IN * HID];      // k-major weights
__device__ float g_W1rootT[F_IN * HID];
__device__ float g_W2relT [HID * OUTF];
__device__ float g_W2rootT[HID * OUTF];
__device__ int   g_mode64;                   // 1 = edge_index is int64, 0 = int32

// ---------------- dtype probe: deterministic function of the input ----------------
__global__ void probe_kernel(const long long* __restrict__ p) {
    if (threadIdx.x == 0 && blockIdx.x == 0) {
        int ok = 1;
        for (int i = 0; i < 64; i++) {
            long long v = p[i];
            if (v < 0 || v >= N_NODES) ok = 0;  // int32 data reinterpreted -> huge values
        }
        g_mode64 = ok;
    }
}

// ---------------- zero the aggregation buffer ----------------
__global__ void zero_agg_kernel() {
    int i = blockIdx.x * blockDim.x + threadIdx.x;
    if (i < N_NODES * (F_IN / 4))
        ((float4*)g_agg)[i] = make_float4(0.f, 0.f, 0.f, 0.f);
}

// ---------------- transpose weights to k-major (tiny, once per launch) ----------------
__global__ void transpose_w_kernel(const float* __restrict__ W1rel,
                                   const float* __restrict__ W1root,
                                   const float* __restrict__ W2rel,
                                   const float* __restrict__ W2root) {
    int i = blockIdx.x * blockDim.x + threadIdx.x;
    if (i < HID * F_IN) {   // W1: [128 x 96] -> [96][128]
        int o = i / F_IN, k = i % F_IN;
        g_W1relT [k * HID + o] = W1rel[i];
        g_W1rootT[k * HID + o] = W1root[i];
    }
    if (i < OUTF * HID) {   // W2: [64 x 128] -> [128][64]
        int o = i / HID, k = i % HID;
        g_W2relT [k * OUTF + o] = W2rel[i];
        g_W2rootT[k * OUTF + o] = W2root[i];
    }
}

// ---------------- layer-1 scatter: agg_x[dst] += x[src]  (96 floats = 24 float4) ----------------
__global__ void scatter_x_kernel(const float* __restrict__ x, const void* __restrict__ ei) {
    const int CH = F_IN / 4;  // 24
    int i = blockIdx.x * blockDim.x + threadIdx.x;
    if (i >= N_EDGES * CH) return;
    int e = i / CH, c = i - e * CH;
    int src, dst;
    if (g_mode64) {
        const long long* p = (const long long*)ei;
        src = (int)__ldg(p + e);
        dst = (int)__ldg(p + N_EDGES + e);
    } else {
        const int* p = (const int*)ei;
        src = __ldg(p + e);
        dst = __ldg(p + N_EDGES + e);
    }
    if (src == dst) return;  // remove_self_loops
    float4 v = __ldg((const float4*)x + (size_t)src * CH + c);
    atomicAdd((float4*)g_agg + (size_t)dst * CH + c, v);  // sm_90+ vector atomic
}

// ---------------- layer-2 scatter: out[dst] += hr[src]  (64 floats = 16 float4) ----------------
__global__ void scatter_hr_kernel(const void* __restrict__ ei, float* __restrict__ out) {
    const int CH = OUTF / 4;  // 16
    int i = blockIdx.x * blockDim.x + threadIdx.x;
    if (i >= N_EDGES * CH) return;
    int e = i / CH, c = i - e * CH;
    int src, dst;
    if (g_mode64) {
        const long long* p = (const long long*)ei;
        src = (int)__ldg(p + e);
        dst = (int)__ldg(p + N_EDGES + e);
    } else {
        const int* p = (const int*)ei;
        src = __ldg(p + e);
        dst = __ldg(p + N_EDGES + e);
    }
    if (src == dst) return;
    float4 v = __ldg((const float4*)g_hr + (size_t)src * CH + c);
    atomicAdd((float4*)out + (size_t)dst * CH + c, v);
}

// ---------------- fused node kernel ----------------
// Per block: 64 nodes, 256 threads (8 warps; each warp owns 8 nodes).
// Stage 1: H[64][128] = relu(agg @ W1rel^T + x @ W1root^T + b1)  -> SMEM
// Stage 2: hr = H @ W2rel^T -> g_hr ;  out = H @ W2root^T + b2 -> d_out
// SMEM: region0 (16384 floats) = sA[64][96] | sX[64][96] | sW1[2][16][128]
//       (reused in stage 2 as W2relT[128][64] | W2rootT[128][64])
//       sH[64][128] (8192 floats).  Total 98304 B -> 2 blocks/SM.
__global__ __launch_bounds__(256, 2)
void fused_kernel(const float* __restrict__ x,
                  const float* __restrict__ b1,
                  const float* __restrict__ b2,
                  float* __restrict__ out) {
    extern __shared__ float smem[];
    float* sA = smem;                    // 6144
    float* sX = smem + NT * F_IN;        // 6144
    float* sW = smem + 2 * NT * F_IN;    // 4096 (two 16x128 chunks)
    float* sH = smem + 16384;            // 8192

    const int tid  = threadIdx.x;
    const int warp = tid >> 5;
    const int lane = tid & 31;
    const int nodeBase = blockIdx.x * NT;

    // ---- load agg & x tiles (node-major, coalesced float4) ----
    #pragma unroll
    for (int t = 0; t < 6; t++) {
        int i = tid + t * 256;            // 0 .. 1535
        int n = i / (F_IN / 4);
        int c = i - n * (F_IN / 4);
        int node = nodeBase + n;
        float4 va = make_float4(0.f, 0.f, 0.f, 0.f), vx = va;
        if (node < N_NODES) {
            va = __ldg((const float4*)g_agg + (size_t)node * (F_IN / 4) + c);
            vx = __ldg((const float4*)x    + (size_t)node * (F_IN / 4) + c);
        }
        ((float4*)sA)[i] = va;
        ((float4*)sX)[i] = vx;
    }

    // ---- stage 1: accumulators seeded with bias ----
    float acc[8][4];
    #pragma unroll
    for (int j = 0; j < 4; j++) {
        float bj = __ldg(b1 + lane + 32 * j);
        #pragma unroll
        for (int n = 0; n < 8; n++) acc[n][j] = bj;
    }

    const int KC = 16;
    for (int kc = 0; kc < F_IN / KC; kc++) {
        __syncthreads();  // protect sW reuse + (iter 0) tile-load completion
        #pragma unroll
        for (int t = 0; t < (KC * HID) / 256; t++) {   // 8 iters
            int i = tid + t * 256;
            sW[i]            = g_W1relT [kc * KC * HID + i];
            sW[KC * HID + i] = g_W1rootT[kc * KC * HID + i];
        }
        __syncthreads();
        #pragma unroll
        for (int kk = 0; kk < KC; kk++) {
            int k = kc * KC + kk;
            float wr[4], wo[4];
            #pragma unroll
            for (int j = 0; j < 4; j++) {
                wr[j] = sW[kk * HID + lane + 32 * j];             // lane-consecutive: conflict-free
                wo[j] = sW[KC * HID + kk * HID + lane + 32 * j];
            }
            #pragma unroll
            for (int n = 0; n < 8; n++) {
                float a  = sA[(warp * 8 + n) * F_IN + k];         // broadcast
                float xv = sX[(warp * 8 + n) * F_IN + k];         // broadcast
                #pragma unroll
                for (int j = 0; j < 4; j++)
                    acc[n][j] = fmaf(a, wr[j], fmaf(xv, wo[j], acc[n][j]));
            }
        }
    }

    // ---- relu -> sH (lane-consecutive stores: conflict-free) ----
    #pragma unroll
    for (int n = 0; n < 8; n++)
        #pragma unroll
        for (int j = 0; j < 4; j++)
            sH[(warp * 8 + n) * HID + lane + 32 * j] = fmaxf(acc[n][j], 0.f);
    __syncthreads();

    // ---- load W2 (k-major) over region0 ----
    #pragma unroll
    for (int t = 0; t < (HID * OUTF) / 256; t++) {  // 32 iters
        int i = tid + t * 256;
        smem[i]              = g_W2relT[i];
        smem[HID * OUTF + i] = g_W2rootT[i];
    }
    __syncthreads();

    // ---- stage 2 ----
    float accR[8][2], accO[8][2];
    #pragma unroll
    for (int j = 0; j < 2; j++) {
        float bj = __ldg(b2 + lane + 32 * j);
        #pragma unroll
        for (int n = 0; n < 8; n++) { accR[n][j] = 0.f; accO[n][j] = bj; }
    }
    #pragma unroll 4
    for (int k = 0; k < HID; k++) {
        float w2r[2], w2o[2];
        #pragma unroll
        for (int j = 0; j < 2; j++) {
            w2r[j] = smem[k * OUTF + lane + 32 * j];
            w2o[j] = smem[HID * OUTF + k * OUTF + lane + 32 * j];
        }
        #pragma unroll
        for (int n = 0; n < 8; n++) {
            float h = sH[(warp * 8 + n) * HID + k];   // broadcast
            #pragma unroll
            for (int j = 0; j < 2; j++) {
                accR[n][j] = fmaf(h, w2r[j], accR[n][j]);
                accO[n][j] = fmaf(h, w2o[j], accO[n][j]);
            }
        }
    }

    // ---- write hr and partial out (root path + bias) ----
    #pragma unroll
    for (int n = 0; n < 8; n++) {
        int node = nodeBase + warp * 8 + n;
        if (node < N_NODES) {
            #pragma unroll
            for (int j = 0; j < 2; j++) {
                g_hr[(size_t)node * OUTF + lane + 32 * j] = accR[n][j];
                out [(size_t)node * OUTF + lane + 32 * j] = accO[n][j];
            }
        }
    }
}

// ---------------- launch ----------------
extern "C" void kernel_launch(void* const* d_in, const int* in_sizes, int n_in,
                              void* d_out, int out_size) {
    const float* x      = (const float*)d_in[0];
    const void*  ei     = d_in[1];
    const float* W1rel  = (const float*)d_in[2];
    const float* b1     = (const float*)d_in[3];
    const float* W1root = (const float*)d_in[4];
    const float* W2rel  = (const float*)d_in[5];
    const float* b2     = (const float*)d_in[6];
    const float* W2root = (const float*)d_in[7];
    float* out = (float*)d_out;

    const int SMEM_BYTES = (16384 + NT * HID) * (int)sizeof(float);  // 98304
    cudaFuncSetAttribute(fused_kernel,
                         cudaFuncAttributeMaxDynamicSharedMemorySize, SMEM_BYTES);

    probe_kernel<<<1, 32>>>((const long long*)ei);
    zero_agg_kernel<<<(N_NODES * (F_IN / 4) + 255) / 256, 256>>>();
    transpose_w_kernel<<<(HID * F_IN + 255) / 256, 256>>>(W1rel, W1root, W2rel, W2root);
    scatter_x_kernel<<<(N_EDGES * (F_IN / 4) + 255) / 256, 256>>>(x, ei);
    fused_kernel<<<(N_NODES + NT - 1) / NT, 256, SMEM_BYTES>>>(x, b1, b2, out);
    scatter_hr_kernel<<<(N_EDGES * (OUTF / 4) + 255) / 256, 256>>>(ei, out);
}

// round 10
// speedup vs baseline: 1.0010x; 1.0007x over previous
#include <cuda_runtime.h>

#define N_NODES 50000
#define F_IN    96
#define HID     128
#define OUTF    64
#define N_EDGES 800000
#define NT      64   // nodes per block in fused kernel

// ---------------- device scratch (allowed: __device__ globals) ----------------
__device__ float g_agg[N_NODES * F_IN];      // layer-1 aggregation  (19.2 MB)
__device__ float g_hr [N_NODES * OUTF];      // h @ W2_rel^T         (12.8 MB)
__device__ float g_W1relT [F_IN * HID];      // k-major weights
__device__ float g_W1rootT[F_IN * HID];
__device__ float g_W2relT [HID * OUTF];
__device__ float g_W2rootT[HID * OUTF];
__device__ int   g_mode64;                   // 1 = edge_index is int64, 0 = int32

// ---------------- dtype probe: deterministic function of the input ----------------
__global__ void probe_kernel(const long long* __restrict__ p) {
    if (threadIdx.x == 0 && blockIdx.x == 0) {
        int ok = 1;
        for (int i = 0; i < 64; i++) {
            long long v = p[i];
            if (v < 0 || v >= N_NODES) ok = 0;  // int32 data reinterpreted -> huge values
        }
        g_mode64 = ok;
    }
}

// ---------------- zero the aggregation buffer ----------------
__global__ void zero_agg_kernel() {
    int i = blockIdx.x * blockDim.x + threadIdx.x;
    if (i < N_NODES * (F_IN / 4))
        ((float4*)g_agg)[i] = make_float4(0.f, 0.f, 0.f, 0.f);
}

// ---------------- transpose weights to k-major (tiny, once per launch) ----------------
__global__ void transpose_w_kernel(const float* __restrict__ W1rel,
                                   const float* __restrict__ W1root,
                                   const float* __restrict__ W2rel,
                                   const float* __restrict__ W2root) {
    int i = blockIdx.x * blockDim.x + threadIdx.x;
    if (i < HID * F_IN) {   // W1: [128 x 96] -> [96][128]
        int o = i / F_IN, k = i % F_IN;
        g_W1relT [k * HID + o] = W1rel[i];
        g_W1rootT[k * HID + o] = W1root[i];
    }
    if (i < OUTF * HID) {   // W2: [64 x 128] -> [128][64]
        int o = i / HID, k = i % HID;
        g_W2relT [k * OUTF + o] = W2rel[i];
        g_W2rootT[k * OUTF + o] = W2root[i];
    }
}

// ---------------- layer-1 scatter: agg_x[dst] += x[src]  (96 floats = 24 float4) ----------------
__global__ void scatter_x_kernel(const float* __restrict__ x, const void* __restrict__ ei) {
    const int CH = F_IN / 4;  // 24
    int i = blockIdx.x * blockDim.x + threadIdx.x;
    if (i >= N_EDGES * CH) return;
    int e = i / CH, c = i - e * CH;
    int src, dst;
    if (g_mode64) {
        const long long* p = (const long long*)ei;
        src = (int)__ldg(p + e);
        dst = (int)__ldg(p + N_EDGES + e);
    } else {
        const int* p = (const int*)ei;
        src = __ldg(p + e);
        dst = __ldg(p + N_EDGES + e);
    }
    if (src == dst) return;  // remove_self_loops
    float4 v = __ldg((const float4*)x + (size_t)src * CH + c);
    atomicAdd((float4*)g_agg + (size_t)dst * CH + c, v);  // sm_90+ vector atomic
}

// ---------------- layer-2 scatter: out[dst] += hr[src]  (64 floats = 16 float4) ----------------
__global__ void scatter_hr_kernel(const void* __restrict__ ei, float* __restrict__ out) {
    const int CH = OUTF / 4;  // 16
    int i = blockIdx.x * blockDim.x + threadIdx.x;
    if (i >= N_EDGES * CH) return;
    int e = i / CH, c = i - e * CH;
    int src, dst;
    if (g_mode64) {
        const long long* p = (const long long*)ei;
        src = (int)__ldg(p + e);
        dst = (int)__ldg(p + N_EDGES + e);
    } else {
        const int* p = (const int*)ei;
        src = __ldg(p + e);
        dst = __ldg(p + N_EDGES + e);
    }
    if (src == dst) return;
    float4 v = __ldg((const float4*)g_hr + (size_t)src * CH + c);
    atomicAdd((float4*)out + (size_t)dst * CH + c, v);
}

// ---------------- fused node kernel ----------------
// Per block: 64 nodes, 256 threads (8 warps; each warp owns 8 nodes).
// Stage 1: H[64][128] = relu(agg @ W1rel^T + x @ W1root^T + b1)  -> SMEM
// Stage 2: hr = H @ W2rel^T -> g_hr ;  out = H @ W2root^T + b2 -> d_out
// SMEM: region0 (16384 floats) = sA[64][96] | sX[64][96] | sW1[2][16][128]
//       (reused in stage 2 as W2relT[128][64] | W2rootT[128][64])
//       sH[64][128] (8192 floats).  Total 98304 B -> 2 blocks/SM.
__global__ __launch_bounds__(256, 2)
void fused_kernel(const float* __restrict__ x,
                  const float* __restrict__ b1,
                  const float* __restrict__ b2,
                  float* __restrict__ out) {
    extern __shared__ float smem[];
    float* sA = smem;                    // 6144
    float* sX = smem + NT * F_IN;        // 6144
    float* sW = smem + 2 * NT * F_IN;    // 4096 (two 16x128 chunks)
    float* sH = smem + 16384;            // 8192

    const int tid  = threadIdx.x;
    const int warp = tid >> 5;
    const int lane = tid & 31;
    const int nodeBase = blockIdx.x * NT;

    // ---- load agg & x tiles (node-major, coalesced float4) ----
    #pragma unroll
    for (int t = 0; t < 6; t++) {
        int i = tid + t * 256;            // 0 .. 1535
        int n = i / (F_IN / 4);
        int c = i - n * (F_IN / 4);
        int node = nodeBase + n;
        float4 va = make_float4(0.f, 0.f, 0.f, 0.f), vx = va;
        if (node < N_NODES) {
            va = __ldg((const float4*)g_agg + (size_t)node * (F_IN / 4) + c);
            vx = __ldg((const float4*)x    + (size_t)node * (F_IN / 4) + c);
        }
        ((float4*)sA)[i] = va;
        ((float4*)sX)[i] = vx;
    }

    // ---- stage 1: accumulators seeded with bias ----
    float acc[8][4];
    #pragma unroll
    for (int j = 0; j < 4; j++) {
        float bj = __ldg(b1 + lane + 32 * j);
        #pragma unroll
        for (int n = 0; n < 8; n++) acc[n][j] = bj;
    }

    const int KC = 16;
    for (int kc = 0; kc < F_IN / KC; kc++) {
        __syncthreads();  // protect sW reuse + (iter 0) tile-load completion
        #pragma unroll
        for (int t = 0; t < (KC * HID) / 256; t++) {   // 8 iters
            int i = tid + t * 256;
            sW[i]            = g_W1relT [kc * KC * HID + i];
            sW[KC * HID + i] = g_W1rootT[kc * KC * HID + i];
        }
        __syncthreads();
        #pragma unroll
        for (int kk = 0; kk < KC; kk++) {
            int k = kc * KC + kk;
            float wr[4], wo[4];
            #pragma unroll
            for (int j = 0; j < 4; j++) {
                wr[j] = sW[kk * HID + lane + 32 * j];             // lane-consecutive: conflict-free
                wo[j] = sW[KC * HID + kk * HID + lane + 32 * j];
            }
            #pragma unroll
            for (int n = 0; n < 8; n++) {
                float a  = sA[(warp * 8 + n) * F_IN + k];         // broadcast
                float xv = sX[(warp * 8 + n) * F_IN + k];         // broadcast
                #pragma unroll
                for (int j = 0; j < 4; j++)
                    acc[n][j] = fmaf(a, wr[j], fmaf(xv, wo[j], acc[n][j]));
            }
        }
    }

    // ---- relu -> sH (lane-consecutive stores: conflict-free) ----
    #pragma unroll
    for (int n = 0; n < 8; n++)
        #pragma unroll
        for (int j = 0; j < 4; j++)
            sH[(warp * 8 + n) * HID + lane + 32 * j] = fmaxf(acc[n][j], 0.f);
    __syncthreads();

    // ---- load W2 (k-major) over region0 ----
    #pragma unroll
    for (int t = 0; t < (HID * OUTF) / 256; t++) {  // 32 iters
        int i = tid + t * 256;
        smem[i]              = g_W2relT[i];
        smem[HID * OUTF + i] = g_W2rootT[i];
    }
    __syncthreads();

    // ---- stage 2 ----
    float accR[8][2], accO[8][2];
    #pragma unroll
    for (int j = 0; j < 2; j++) {
        float bj = __ldg(b2 + lane + 32 * j);
        #pragma unroll
        for (int n = 0; n < 8; n++) { accR[n][j] = 0.f; accO[n][j] = bj; }
    }
    #pragma unroll 4
    for (int k = 0; k < HID; k++) {
        float w2r[2], w2o[2];
        #pragma unroll
        for (int j = 0; j < 2; j++) {
            w2r[j] = smem[k * OUTF + lane + 32 * j];
            w2o[j] = smem[HID * OUTF + k * OUTF + lane + 32 * j];
        }
        #pragma unroll
        for (int n = 0; n < 8; n++) {
            float h = sH[(warp * 8 + n) * HID + k];   // broadcast
            #pragma unroll
            for (int j = 0; j < 2; j++) {
                accR[n][j] = fmaf(h, w2r[j], accR[n][j]);
                accO[n][j] = fmaf(h, w2o[j], accO[n][j]);
            }
        }
    }

    // ---- write hr and partial out (root path + bias) ----
    #pragma unroll
    for (int n = 0; n < 8; n++) {
        int node = nodeBase + warp * 8 + n;
        if (node < N_NODES) {
            #pragma unroll
            for (int j = 0; j < 2; j++) {
                g_hr[(size_t)node * OUTF + lane + 32 * j] = accR[n][j];
                out [(size_t)node * OUTF + lane + 32 * j] = accO[n][j];
            }
        }
    }
}

// ---------------- launch ----------------
extern "C" void kernel_launch(void* const* d_in, const int* in_sizes, int n_in,
                              void* d_out, int out_size) {
    const float* x      = (const float*)d_in[0];
    const void*  ei     = d_in[1];
    const float* W1rel  = (const float*)d_in[2];
    const float* b1     = (const float*)d_in[3];
    const float* W1root = (const float*)d_in[4];
    const float* W2rel  = (const float*)d_in[5];
    const float* b2     = (const float*)d_in[6];
    const float* W2root = (const float*)d_in[7];
    float* out = (float*)d_out;

    const int SMEM_BYTES = (16384 + NT * HID) * (int)sizeof(float);  // 98304
    cudaFuncSetAttribute(fused_kernel,
                         cudaFuncAttributeMaxDynamicSharedMemorySize, SMEM_BYTES);

    probe_kernel<<<1, 32>>>((const long long*)ei);
    zero_agg_kernel<<<(N_NODES * (F_IN / 4) + 255) / 256, 256>>>();
    transpose_w_kernel<<<(HID * F_IN + 255) / 256, 256>>>(W1rel, W1root, W2rel, W2root);
    scatter_x_kernel<<<(N_EDGES * (F_IN / 4) + 255) / 256, 256>>>(x, ei);
    fused_kernel<<<(N_NODES + NT - 1) / NT, 256, SMEM_BYTES>>>(x, b1, b2, out);
    scatter_hr_kernel<<<(N_EDGES * (OUTF / 4) + 255) / 256, 256>>>(ei, out);
}

// round 11
// speedup vs baseline: 1.0060x; 1.0050x over previous
#include <cuda_runtime.h>

#define N_NODES 50000
#define F_IN    96
#define HID     128
#define OUTF    64
#define N_EDGES 800000
#define NT      64   // nodes per block in fused kernel

// ---------------- device scratch (allowed: __device__ globals) ----------------
__device__ float g_agg[N_NODES * F_IN];      // layer-1 aggregation  (19.2 MB)
__device__ float g_hr [N_NODES * OUTF];      // h @ W2_rel^T         (12.8 MB)
__device__ float g_W1relT [F_IN * HID];      // k-major weights
__device__ float g_W1rootT[F_IN * HID];
__device__ float g_W2relT [HID * OUTF];
__device__ float g_W2rootT[HID * OUTF];
__device__ int   g_mode64;                   // 1 = edge_index is int64, 0 = int32

// ---------------- dtype probe: deterministic function of the input ----------------
__global__ void probe_kernel(const long long* __restrict__ p) {
    if (threadIdx.x == 0 && blockIdx.x == 0) {
        int ok = 1;
        for (int i = 0; i < 64; i++) {
            long long v = p[i];
            if (v < 0 || v >= N_NODES) ok = 0;  // int32 data reinterpreted -> huge values
        }
        g_mode64 = ok;
    }
}

// ---------------- zero the aggregation buffer ----------------
__global__ void zero_agg_kernel() {
    int i = blockIdx.x * blockDim.x + threadIdx.x;
    if (i < N_NODES * (F_IN / 4))
        ((float4*)g_agg)[i] = make_float4(0.f, 0.f, 0.f, 0.f);
}

// ---------------- transpose weights to k-major (tiny, once per launch) ----------------
__global__ void transpose_w_kernel(const float* __restrict__ W1rel,
                                   const float* __restrict__ W1root,
                                   const float* __restrict__ W2rel,
                                   const float* __restrict__ W2root) {
    int i = blockIdx.x * blockDim.x + threadIdx.x;
    if (i < HID * F_IN) {   // W1: [128 x 96] -> [96][128]
        int o = i / F_IN, k = i % F_IN;
        g_W1relT [k * HID + o] = W1rel[i];
        g_W1rootT[k * HID + o] = W1root[i];
    }
    if (i < OUTF * HID) {   // W2: [64 x 128] -> [128][64]
        int o = i / HID, k = i % HID;
        g_W2relT [k * OUTF + o] = W2rel[i];
        g_W2rootT[k * OUTF + o] = W2root[i];
    }
}

// ---------------- layer-1 scatter: agg_x[dst] += x[src]  (96 floats = 24 float4) ----------------
__global__ void scatter_x_kernel(const float* __restrict__ x, const void* __restrict__ ei) {
    const int CH = F_IN / 4;  // 24
    int i = blockIdx.x * blockDim.x + threadIdx.x;
    if (i >= N_EDGES * CH) return;
    int e = i / CH, c = i - e * CH;
    int src, dst;
    if (g_mode64) {
        const long long* p = (const long long*)ei;
        src = (int)__ldg(p + e);
        dst = (int)__ldg(p + N_EDGES + e);
    } else {
        const int* p = (const int*)ei;
        src = __ldg(p + e);
        dst = __ldg(p + N_EDGES + e);
    }
    if (src == dst) return;  // remove_self_loops
    float4 v = __ldg((const float4*)x + (size_t)src * CH + c);
    atomicAdd((float4*)g_agg + (size_t)dst * CH + c, v);  // sm_90+ vector atomic
}

// ---------------- layer-2 scatter: out[dst] += hr[src]  (64 floats = 16 float4) ----------------
__global__ void scatter_hr_kernel(const void* __restrict__ ei, float* __restrict__ out) {
    const int CH = OUTF / 4;  // 16
    int i = blockIdx.x * blockDim.x + threadIdx.x;
    if (i >= N_EDGES * CH) return;
    int e = i / CH, c = i - e * CH;
    int src, dst;
    if (g_mode64) {
        const long long* p = (const long long*)ei;
        src = (int)__ldg(p + e);
        dst = (int)__ldg(p + N_EDGES + e);
    } else {
        const int* p = (const int*)ei;
        src = __ldg(p + e);
        dst = __ldg(p + N_EDGES + e);
    }
    if (src == dst) return;
    float4 v = __ldg((const float4*)g_hr + (size_t)src * CH + c);
    atomicAdd((float4*)out + (size_t)dst * CH + c, v);
}

// ---------------- fused node kernel ----------------
// Per block: 64 nodes, 256 threads (8 warps; each warp owns 8 nodes).
// Stage 1: H[64][128] = relu(agg @ W1rel^T + x @ W1root^T + b1)  -> SMEM
// Stage 2: hr = H @ W2rel^T -> g_hr ;  out = H @ W2root^T + b2 -> d_out
// SMEM: region0 (16384 floats) = sA[64][96] | sX[64][96] | sW1[2][16][128]
//       (reused in stage 2 as W2relT[128][64] | W2rootT[128][64])
//       sH[64][128] (8192 floats).  Total 98304 B -> 2 blocks/SM.
__global__ __launch_bounds__(256, 2)
void fused_kernel(const float* __restrict__ x,
                  const float* __restrict__ b1,
                  const float* __restrict__ b2,
                  float* __restrict__ out) {
    extern __shared__ float smem[];
    float* sA = smem;                    // 6144
    float* sX = smem + NT * F_IN;        // 6144
    float* sW = smem + 2 * NT * F_IN;    // 4096 (two 16x128 chunks)
    float* sH = smem + 16384;            // 8192

    const int tid  = threadIdx.x;
    const int warp = tid >> 5;
    const int lane = tid & 31;
    const int nodeBase = blockIdx.x * NT;

    // ---- load agg & x tiles (node-major, coalesced float4) ----
    #pragma unroll
    for (int t = 0; t < 6; t++) {
        int i = tid + t * 256;            // 0 .. 1535
        int n = i / (F_IN / 4);
        int c = i - n * (F_IN / 4);
        int node = nodeBase + n;
        float4 va = make_float4(0.f, 0.f, 0.f, 0.f), vx = va;
        if (node < N_NODES) {
            va = __ldg((const float4*)g_agg + (size_t)node * (F_IN / 4) + c);
            vx = __ldg((const float4*)x    + (size_t)node * (F_IN / 4) + c);
        }
        ((float4*)sA)[i] = va;
        ((float4*)sX)[i] = vx;
    }

    // ---- stage 1: accumulators seeded with bias ----
    float acc[8][4];
    #pragma unroll
    for (int j = 0; j < 4; j++) {
        float bj = __ldg(b1 + lane + 32 * j);
        #pragma unroll
        for (int n = 0; n < 8; n++) acc[n][j] = bj;
    }

    const int KC = 16;
    for (int kc = 0; kc < F_IN / KC; kc++) {
        __syncthreads();  // protect sW reuse + (iter 0) tile-load completion
        #pragma unroll
        for (int t = 0; t < (KC * HID) / 256; t++) {   // 8 iters
            int i = tid + t * 256;
            sW[i]            = g_W1relT [kc * KC * HID + i];
            sW[KC * HID + i] = g_W1rootT[kc * KC * HID + i];
        }
        __syncthreads();
        #pragma unroll
        for (int kk = 0; kk < KC; kk++) {
            int k = kc * KC + kk;
            float wr[4], wo[4];
            #pragma unroll
            for (int j = 0; j < 4; j++) {
                wr[j] = sW[kk * HID + lane + 32 * j];             // lane-consecutive: conflict-free
                wo[j] = sW[KC * HID + kk * HID + lane + 32 * j];
            }
            #pragma unroll
            for (int n = 0; n < 8; n++) {
                float a  = sA[(warp * 8 + n) * F_IN + k];         // broadcast
                float xv = sX[(warp * 8 + n) * F_IN + k];         // broadcast
                #pragma unroll
                for (int j = 0; j < 4; j++)
                    acc[n][j] = fmaf(a, wr[j], fmaf(xv, wo[j], acc[n][j]));
            }
        }
    }

    // ---- relu -> sH (lane-consecutive stores: conflict-free) ----
    #pragma unroll
    for (int n = 0; n < 8; n++)
        #pragma unroll
        for (int j = 0; j < 4; j++)
            sH[(warp * 8 + n) * HID + lane + 32 * j] = fmaxf(acc[n][j], 0.f);
    __syncthreads();

    // ---- load W2 (k-major) over region0 ----
    #pragma unroll
    for (int t = 0; t < (HID * OUTF) / 256; t++) {  // 32 iters
        int i = tid + t * 256;
        smem[i]              = g_W2relT[i];
        smem[HID * OUTF + i] = g_W2rootT[i];
    }
    __syncthreads();

    // ---- stage 2 ----
    float accR[8][2], accO[8][2];
    #pragma unroll
    for (int j = 0; j < 2; j++) {
        float bj = __ldg(b2 + lane + 32 * j);
        #pragma unroll
        for (int n = 0; n < 8; n++) { accR[n][j] = 0.f; accO[n][j] = bj; }
    }
    #pragma unroll 4
    for (int k = 0; k < HID; k++) {
        float w2r[2], w2o[2];
        #pragma unroll
        for (int j = 0; j < 2; j++) {
            w2r[j] = smem[k * OUTF + lane + 32 * j];
            w2o[j] = smem[HID * OUTF + k * OUTF + lane + 32 * j];
        }
        #pragma unroll
        for (int n = 0; n < 8; n++) {
            float h = sH[(warp * 8 + n) * HID + k];   // broadcast
            #pragma unroll
            for (int j = 0; j < 2; j++) {
                accR[n][j] = fmaf(h, w2r[j], accR[n][j]);
                accO[n][j] = fmaf(h, w2o[j], accO[n][j]);
            }
        }
    }

    // ---- write hr and partial out (root path + bias) ----
    #pragma unroll
    for (int n = 0; n < 8; n++) {
        int node = nodeBase + warp * 8 + n;
        if (node < N_NODES) {
            #pragma unroll
            for (int j = 0; j < 2; j++) {
                g_hr[(size_t)node * OUTF + lane + 32 * j] = accR[n][j];
                out [(size_t)node * OUTF + lane + 32 * j] = accO[n][j];
            }
        }
    }
}

// ---------------- launch ----------------
extern "C" void kernel_launch(void* const* d_in, const int* in_sizes, int n_in,
                              void* d_out, int out_size) {
    const float* x      = (const float*)d_in[0];
    const void*  ei     = d_in[1];
    const float* W1rel  = (const float*)d_in[2];
    const float* b1     = (const float*)d_in[3];
    const float* W1root = (const float*)d_in[4];
    const float* W2rel  = (const float*)d_in[5];
    const float* b2     = (const float*)d_in[6];
    const float* W2root = (const float*)d_in[7];
    float* out = (float*)d_out;

    const int SMEM_BYTES = (16384 + NT * HID) * (int)sizeof(float);  // 98304
    cudaFuncSetAttribute(fused_kernel,
                         cudaFuncAttributeMaxDynamicSharedMemorySize, SMEM_BYTES);

    probe_kernel<<<1, 32>>>((const long long*)ei);
    zero_agg_kernel<<<(N_NODES * (F_IN / 4) + 255) / 256, 256>>>();
    transpose_w_kernel<<<(HID * F_IN + 255) / 256, 256>>>(W1rel, W1root, W2rel, W2root);
    scatter_x_kernel<<<(N_EDGES * (F_IN / 4) + 255) / 256, 256>>>(x, ei);
    fused_kernel<<<(N_NODES + NT - 1) / NT, 256, SMEM_BYTES>>>(x, b1, b2, out);
    scatter_hr_kernel<<<(N_EDGES * (OUTF / 4) + 255) / 256, 256>>>(ei, out);
}